// round 2
// baseline (speedup 1.0000x reference)
#include <cuda_runtime.h>

#define N_PTS 32768
#define M_PTS 8192
#define D_DIM 64
#define BM 128
#define BN 64
#define NTHREADS 256
#define NBLOCKS (N_PTS / BM)

__device__ float g_b[M_PTS];            // y2_j - psi_j
__device__ float g_partials[NBLOCKS];   // per-block sums of (x2_i + min_j ...)

// ---------------------------------------------------------------------------
// Kernel 1: b_j = ||y_j||^2 - psi_j
// ---------------------------------------------------------------------------
__global__ void prep_b_kernel(const float* __restrict__ y,
                              const float* __restrict__ psi) {
    int j = blockIdx.x * blockDim.x + threadIdx.x;
    if (j < M_PTS) {
        const float* yr = y + (size_t)j * D_DIM;
        float s = 0.f;
#pragma unroll
        for (int k = 0; k < D_DIM; k++) s = fmaf(yr[k], yr[k], s);
        g_b[j] = s - psi[j];
    }
}

// ---------------------------------------------------------------------------
// Kernel 2: for each block of BM x-rows, stream all M y-rows through shared
// memory, computing dot products and a running min of (b_j - 2<x,y>).
// Thread layout: tx = tid & 15 -> j (TN=4), ty = tid >> 4 -> i (TM=8).
// ---------------------------------------------------------------------------
__global__ __launch_bounds__(NTHREADS)
void semidual_main_kernel(const float* __restrict__ x,
                          const float* __restrict__ y) {
    __shared__ float xs[D_DIM][BM];   // transposed x tile: xs[k][i]
    __shared__ float ys[D_DIM][BN];   // transposed y tile: ys[k][j]
    __shared__ float bs[BN];
    __shared__ float x2s[BM];
    __shared__ float red[16];

    const int tid = threadIdx.x;
    const int tx = tid & 15;
    const int ty = tid >> 4;
    const int i0 = blockIdx.x * BM;

    // Load x tile (once), transposed. idx = c4*BM + row so shared stores are
    // conflict-free (consecutive tid -> consecutive i at same k).
    for (int idx = tid; idx < BM * (D_DIM / 4); idx += NTHREADS) {
        int c4  = idx >> 7;        // 0..15
        int row = idx & (BM - 1);  // 0..127
        float4 v = *(const float4*)(x + (size_t)(i0 + row) * D_DIM + c4 * 4);
        xs[c4 * 4 + 0][row] = v.x;
        xs[c4 * 4 + 1][row] = v.y;
        xs[c4 * 4 + 2][row] = v.z;
        xs[c4 * 4 + 3][row] = v.w;
    }
    __syncthreads();

    // x2_i for this tile (conflict-free: consecutive tid -> consecutive i)
    if (tid < BM) {
        float s = 0.f;
#pragma unroll
        for (int k = 0; k < D_DIM; k++) {
            float t = xs[k][tid];
            s = fmaf(t, t, s);
        }
        x2s[tid] = s;
    }

    float rmin[8];
#pragma unroll
    for (int im = 0; im < 8; im++) rmin[im] = 3.4e38f;

    for (int jt = 0; jt < M_PTS; jt += BN) {
        __syncthreads();  // previous iteration done reading ys/bs
        // Load y tile transposed + bs
        for (int idx = tid; idx < BN * (D_DIM / 4); idx += NTHREADS) {
            int c4  = idx >> 6;        // 0..15
            int row = idx & (BN - 1);  // 0..63
            float4 v = *(const float4*)(y + (size_t)(jt + row) * D_DIM + c4 * 4);
            ys[c4 * 4 + 0][row] = v.x;
            ys[c4 * 4 + 1][row] = v.y;
            ys[c4 * 4 + 2][row] = v.z;
            ys[c4 * 4 + 3][row] = v.w;
        }
        if (tid < BN) bs[tid] = g_b[jt + tid];
        __syncthreads();

        float acc[8][4];
#pragma unroll
        for (int a = 0; a < 8; a++)
#pragma unroll
            for (int b = 0; b < 4; b++) acc[a][b] = 0.f;

#pragma unroll
        for (int k = 0; k < D_DIM; k++) {
            float4 a0 = *(float4*)&xs[k][ty * 8];
            float4 a1 = *(float4*)&xs[k][ty * 8 + 4];
            float4 bb = *(float4*)&ys[k][tx * 4];
            float av[8] = {a0.x, a0.y, a0.z, a0.w, a1.x, a1.y, a1.z, a1.w};
            float bv[4] = {bb.x, bb.y, bb.z, bb.w};
#pragma unroll
            for (int im = 0; im < 8; im++)
#pragma unroll
                for (int jn = 0; jn < 4; jn++)
                    acc[im][jn] = fmaf(av[im], bv[jn], acc[im][jn]);
        }

#pragma unroll
        for (int jn = 0; jn < 4; jn++) {
            float bj = bs[tx * 4 + jn];
#pragma unroll
            for (int im = 0; im < 8; im++) {
                float v = fmaf(-2.f, acc[im][jn], bj);
                rmin[im] = fminf(rmin[im], v);
            }
        }
    }

    // Min-reduce across the 16 j-threads (tx) via 16-wide shuffles
#pragma unroll
    for (int im = 0; im < 8; im++) {
#pragma unroll
        for (int m = 8; m >= 1; m >>= 1)
            rmin[im] = fminf(rmin[im],
                             __shfl_xor_sync(0xffffffffu, rmin[im], m, 16));
    }

    if (tx == 0) {
        float s = 0.f;
#pragma unroll
        for (int im = 0; im < 8; im++) s += x2s[ty * 8 + im] + rmin[im];
        red[ty] = s;
    }
    __syncthreads();
    if (tid == 0) {
        float s = 0.f;
#pragma unroll
        for (int t = 0; t < 16; t++) s += red[t];
        g_partials[blockIdx.x] = s;
    }
}

// ---------------------------------------------------------------------------
// Kernel 3: deterministic final reduction + mean(psi)
// ---------------------------------------------------------------------------
__global__ void finalize_kernel(const float* __restrict__ psi,
                                float* __restrict__ out) {
    __shared__ float sh[256];
    int tid = threadIdx.x;
    float s = 0.f;
    for (int b = tid; b < NBLOCKS; b += 256) s += g_partials[b];
    s *= (1.0f / N_PTS);
    float p = 0.f;
    for (int j = tid; j < M_PTS; j += 256) p += psi[j];
    s = fmaf(p, 1.0f / M_PTS, s);
    sh[tid] = s;
    __syncthreads();
    for (int off = 128; off > 0; off >>= 1) {
        if (tid < off) sh[tid] += sh[tid + off];
        __syncthreads();
    }
    if (tid == 0) out[0] = sh[0];
}

extern "C" void kernel_launch(void* const* d_in, const int* in_sizes, int n_in,
                              void* d_out, int out_size) {
    const float* x   = (const float*)d_in[0];   // [N, D]
    const float* y   = (const float*)d_in[1];   // [M, D]
    const float* psi = (const float*)d_in[2];   // [M]
    float* out = (float*)d_out;

    prep_b_kernel<<<(M_PTS + 255) / 256, 256>>>(y, psi);
    semidual_main_kernel<<<NBLOCKS, NTHREADS>>>(x, y);
    finalize_kernel<<<1, 256>>>(psi, out);
}

// round 4
// speedup vs baseline: 1.7998x; 1.7998x over previous
#include <cuda_runtime.h>
#include <cuda_bf16.h>
#include <cstdint>

#define N_PTS 32768
#define M_PTS 8192
#define D_DIM 64
#define BM 128
#define BN 128
#define NTILES (M_PTS / BN)          // 64
#define NBLOCKS (N_PTS / BM)         // 256

// dynamic smem layout (bytes)
#define OFF_XH   0
#define OFF_XL   16384
#define OFF_Y    32768               // + buf*32768 + part*16384
#define OFF_BS   98304               // 2 * 128 * 4
#define OFF_X2S  99328               // 128 * 4
#define OFF_ROWRED 99840             // 4 * 128 * 4
#define OFF_RED  101888              // 4 * 4
#define SMEM_TOTAL 101952

__device__ __nv_bfloat16 g_xh[N_PTS * D_DIM];
__device__ __nv_bfloat16 g_xl[N_PTS * D_DIM];
__device__ __nv_bfloat16 g_yh[M_PTS * D_DIM];
__device__ __nv_bfloat16 g_yl[M_PTS * D_DIM];
__device__ float g_b[M_PTS];
__device__ float g_partials[NBLOCKS];

__device__ __forceinline__ uint32_t smem_u32(const void* p) {
    uint32_t a;
    asm("{ .reg .u64 t; cvta.to.shared.u64 t, %1; cvt.u32.u64 %0, t; }" : "=r"(a) : "l"(p));
    return a;
}

#define CP_ASYNC16(s, g) \
    asm volatile("cp.async.cg.shared.global [%0], [%1], 16;" :: "r"(s), "l"(g))
#define CP_COMMIT() asm volatile("cp.async.commit_group;" ::: "memory")
#define CP_WAIT0()  asm volatile("cp.async.wait_group 0;" ::: "memory")

#define LDSM4(r, addr) \
    asm volatile("ldmatrix.sync.aligned.m8n8.x4.shared.b16 {%0,%1,%2,%3}, [%4];" \
                 : "=r"((r)[0]), "=r"((r)[1]), "=r"((r)[2]), "=r"((r)[3]) : "r"(addr))

#define MMA_BF16(c, a, b0, b1) \
    asm volatile("mma.sync.aligned.m16n8k16.row.col.f32.bf16.bf16.f32 " \
                 "{%0,%1,%2,%3},{%4,%5,%6,%7},{%8,%9},{%0,%1,%2,%3};" \
                 : "+f"((c)[0]), "+f"((c)[1]), "+f"((c)[2]), "+f"((c)[3]) \
                 : "r"((a)[0]), "r"((a)[1]), "r"((a)[2]), "r"((a)[3]), "r"(b0), "r"(b1))

// ---------------------------------------------------------------------------
// Prep: bf16 hi/lo split of x and y; b_j = ||y_j||^2 - psi_j (fp32)
// ---------------------------------------------------------------------------
__global__ void prep_kernel(const float* __restrict__ x,
                            const float* __restrict__ y,
                            const float* __restrict__ psi) {
    int idx = blockIdx.x * blockDim.x + threadIdx.x;
    if (idx < N_PTS * D_DIM) {
        float v = x[idx];
        __nv_bfloat16 h = __float2bfloat16(v);
        g_xh[idx] = h;
        g_xl[idx] = __float2bfloat16(v - __bfloat162float(h));
    }
    if (idx < M_PTS * D_DIM) {
        float v = y[idx];
        __nv_bfloat16 h = __float2bfloat16(v);
        g_yh[idx] = h;
        g_yl[idx] = __float2bfloat16(v - __bfloat162float(h));
    }
    if (idx < M_PTS) {
        const float* yr = y + (size_t)idx * D_DIM;
        float s = 0.f;
#pragma unroll
        for (int k = 0; k < D_DIM; k++) s = fmaf(yr[k], yr[k], s);
        g_b[idx] = s - psi[idx];
    }
}

// ---------------------------------------------------------------------------
// Main: warp-level bf16 mma with hi/lo split, fused min-epilogue.
// 8 warps: warp_m = w>>2 (2), warp_n = w&3 (4); warp tile 64 x 32.
// SMEM tiles: 128 rows x 64 bf16 (128 B/row), 16B-chunk swizzle c ^ (row&7).
// ---------------------------------------------------------------------------
__global__ __launch_bounds__(256)
void semidual_mma_kernel(const float* __restrict__ x) {
    extern __shared__ char smem[];
    const uint32_t sb = smem_u32(smem);
    const int tid  = threadIdx.x;
    const int lane = tid & 31;
    const int w    = tid >> 5;
    const int wm   = w >> 2;
    const int wn   = w & 3;
    const int i0   = blockIdx.x * BM;

    // cp.async one [128 x 64] bf16 tile with swizzled stores (4 chunks/thread)
    auto tile_cp = [&](const __nv_bfloat16* g, int row0, uint32_t soff) {
        const char* gp = (const char*)(g + (size_t)row0 * D_DIM);
#pragma unroll
        for (int it = 0; it < 4; it++) {
            int c   = it * 256 + tid;        // 0..1023
            int row = c >> 3, col = c & 7;
            uint32_t so = sb + soff + row * 128 + ((col ^ (row & 7)) << 4);
            CP_ASYNC16(so, gp + (size_t)c * 16);
        }
    };

    // prologue: x tiles + y tile 0
    tile_cp(g_xh, i0, OFF_XH);
    tile_cp(g_xl, i0, OFF_XL);
    tile_cp(g_yh, 0, OFF_Y);
    tile_cp(g_yl, 0, OFF_Y + 16384);
    CP_COMMIT();

    if (tid < BM) {
        // x2 for row i0+tid
        const float4* xr = (const float4*)(x + (size_t)(i0 + tid) * D_DIM);
        float x2 = 0.f;
#pragma unroll
        for (int q = 0; q < 16; q++) {
            float4 v = xr[q];
            x2 = fmaf(v.x, v.x, x2); x2 = fmaf(v.y, v.y, x2);
            x2 = fmaf(v.z, v.z, x2); x2 = fmaf(v.w, v.w, x2);
        }
        ((float*)(smem + OFF_X2S))[tid] = x2;
        ((float*)(smem + OFF_BS))[tid] = g_b[tid];
    }
    CP_WAIT0();
    __syncthreads();

    // per-lane invariant addressing pieces
    const uint32_t aoff  = (uint32_t)(wm * 64 + (lane & 15)) * 128;
    const int      cselA = lane >> 4;
    const int      axorA = (lane & 7);
    const uint32_t boff  = (uint32_t)(wn * 32 + ((lane >> 4) << 3) + (lane & 7)) * 128;
    const int      cselB = (lane >> 3) & 1;
    const int      bxorB = (lane & 7);

    float rmin[8];
#pragma unroll
    for (int r = 0; r < 8; r++) rmin[r] = 3.4e38f;

    for (int t = 0; t < NTILES; t++) {
        const int b = t & 1, nb = b ^ 1;
        if (t + 1 < NTILES) {
            tile_cp(g_yh, (t + 1) * BN, OFF_Y + nb * 32768);
            tile_cp(g_yl, (t + 1) * BN, OFF_Y + nb * 32768 + 16384);
            CP_COMMIT();
            if (tid < BN)
                ((float*)(smem + OFF_BS))[nb * BN + tid] = g_b[(t + 1) * BN + tid];
        }

        const uint32_t ybh = sb + OFF_Y + b * 32768;
        const uint32_t ybl = ybh + 16384;
        const uint32_t axh = sb + OFF_XH;
        const uint32_t axl = sb + OFF_XL;

        float c[4][4][4];
#pragma unroll
        for (int mt = 0; mt < 4; mt++)
#pragma unroll
            for (int nt = 0; nt < 4; nt++)
#pragma unroll
                for (int q = 0; q < 4; q++) c[mt][nt][q] = 0.f;

#pragma unroll
        for (int kb = 0; kb < 4; kb++) {
            const uint32_t ca = (uint32_t)(((2 * kb + cselA) ^ axorA) << 4);
            const uint32_t cb = (uint32_t)(((2 * kb + cselB) ^ bxorB) << 4);
            uint32_t a[4][4], bh[2][4], bl[2][4];
#pragma unroll
            for (int mt = 0; mt < 4; mt++) LDSM4(a[mt], axh + aoff + mt * 2048 + ca);
#pragma unroll
            for (int np = 0; np < 2; np++) LDSM4(bh[np], ybh + boff + np * 2048 + cb);
#pragma unroll
            for (int np = 0; np < 2; np++) LDSM4(bl[np], ybl + boff + np * 2048 + cb);
            // hh
#pragma unroll
            for (int mt = 0; mt < 4; mt++)
#pragma unroll
                for (int nt = 0; nt < 4; nt++)
                    MMA_BF16(c[mt][nt], a[mt], bh[nt >> 1][(nt & 1) * 2], bh[nt >> 1][(nt & 1) * 2 + 1]);
            // hl
#pragma unroll
            for (int mt = 0; mt < 4; mt++)
#pragma unroll
                for (int nt = 0; nt < 4; nt++)
                    MMA_BF16(c[mt][nt], a[mt], bl[nt >> 1][(nt & 1) * 2], bl[nt >> 1][(nt & 1) * 2 + 1]);
            // lh (reuse a regs)
#pragma unroll
            for (int mt = 0; mt < 4; mt++) LDSM4(a[mt], axl + aoff + mt * 2048 + ca);
#pragma unroll
            for (int mt = 0; mt < 4; mt++)
#pragma unroll
                for (int nt = 0; nt < 4; nt++)
                    MMA_BF16(c[mt][nt], a[mt], bh[nt >> 1][(nt & 1) * 2], bh[nt >> 1][(nt & 1) * 2 + 1]);
        }

        // epilogue: min of (b_j - 2*dot) over this tile's 32 cols (per lane: 8)
        const float* bsf = (const float*)(smem + OFF_BS) + b * BN;
#pragma unroll
        for (int nt = 0; nt < 4; nt++) {
            const int j0 = wn * 32 + nt * 8 + (lane & 3) * 2;
            const float b0 = bsf[j0], b1 = bsf[j0 + 1];
#pragma unroll
            for (int mt = 0; mt < 4; mt++) {
                float v0 = fminf(fmaf(-2.f, c[mt][nt][0], b0), fmaf(-2.f, c[mt][nt][1], b1));
                float v1 = fminf(fmaf(-2.f, c[mt][nt][2], b0), fmaf(-2.f, c[mt][nt][3], b1));
                rmin[mt * 2]     = fminf(rmin[mt * 2], v0);
                rmin[mt * 2 + 1] = fminf(rmin[mt * 2 + 1], v1);
            }
        }

        CP_WAIT0();
        __syncthreads();
    }

    // min over the 4 lanes of each row group (tig = lane&3)
#pragma unroll
    for (int r = 0; r < 8; r++) {
        rmin[r] = fminf(rmin[r], __shfl_xor_sync(0xffffffffu, rmin[r], 1));
        rmin[r] = fminf(rmin[r], __shfl_xor_sync(0xffffffffu, rmin[r], 2));
    }
    float* rowred = (float*)(smem + OFF_ROWRED);
    if ((lane & 3) == 0) {
        const int g = lane >> 2;
#pragma unroll
        for (int mt = 0; mt < 4; mt++) {
            const int r0 = wm * 64 + mt * 16 + g;
            rowred[wn * BM + r0]     = rmin[mt * 2];
            rowred[wn * BM + r0 + 8] = rmin[mt * 2 + 1];
        }
    }
    __syncthreads();
    if (tid < BM) {
        float m = fminf(fminf(rowred[tid], rowred[BM + tid]),
                        fminf(rowred[2 * BM + tid], rowred[3 * BM + tid]));
        float v = ((const float*)(smem + OFF_X2S))[tid] + m;
#pragma unroll
        for (int s = 16; s >= 1; s >>= 1) v += __shfl_xor_sync(0xffffffffu, v, s);
        if (lane == 0) ((float*)(smem + OFF_RED))[tid >> 5] = v;
    }
    __syncthreads();
    if (tid == 0) {
        const float* rd = (const float*)(smem + OFF_RED);
        g_partials[blockIdx.x] = rd[0] + rd[1] + rd[2] + rd[3];
    }
}

// ---------------------------------------------------------------------------
// Finalize: deterministic reduction + mean(psi)
// ---------------------------------------------------------------------------
__global__ void finalize_kernel(const float* __restrict__ psi,
                                float* __restrict__ out) {
    __shared__ float sh[256];
    int tid = threadIdx.x;
    float s = 0.f;
    for (int b = tid; b < NBLOCKS; b += 256) s += g_partials[b];
    s *= (1.0f / N_PTS);
    float p = 0.f;
    for (int j = tid; j < M_PTS; j += 256) p += psi[j];
    s = fmaf(p, 1.0f / M_PTS, s);
    sh[tid] = s;
    __syncthreads();
    for (int off = 128; off > 0; off >>= 1) {
        if (tid < off) sh[tid] += sh[tid + off];
        __syncthreads();
    }
    if (tid == 0) out[0] = sh[0];
}

extern "C" void kernel_launch(void* const* d_in, const int* in_sizes, int n_in,
                              void* d_out, int out_size) {
    (void)in_sizes; (void)n_in; (void)out_size;
    const float* x   = (const float*)d_in[0];   // [N, D]
    const float* y   = (const float*)d_in[1];   // [M, D]
    const float* psi = (const float*)d_in[2];   // [M]
    float* out = (float*)d_out;

    cudaFuncSetAttribute(semidual_mma_kernel,
                         cudaFuncAttributeMaxDynamicSharedMemorySize, SMEM_TOTAL);

    prep_kernel<<<(N_PTS * D_DIM) / 256, 256>>>(x, y, psi);
    semidual_mma_kernel<<<NBLOCKS, 256, SMEM_TOTAL>>>(x);
    finalize_kernel<<<1, 256>>>(psi, out);
}

// round 5
// speedup vs baseline: 4.7115x; 2.6178x over previous
#include <cuda_runtime.h>
#include <cuda_fp16.h>
#include <cstdint>

#define N_PTS 32768
#define M_PTS 8192
#define D_DIM 64
#define BM 128
#define BN 128
#define NTILES (M_PTS / BN)          // 64
#define NBLOCKS (N_PTS / BM)         // 256

// dynamic smem layout (bytes)
#define OFF_XH     0                 // 16384
#define OFF_XL     16384             // 16384
#define OFF_Y      32768             // 2 * 16384 (double-buffered y-hi)
#define OFF_BS     65536             // 2 * 128 * 4
#define OFF_X2S    66560             // 128 * 4
#define OFF_ROWRED 67072             // 4 * 128 * 4
#define OFF_RED    69120             // 16
#define SMEM_TOTAL 69184

__device__ __half g_xh[N_PTS * D_DIM];
__device__ __half g_xl[N_PTS * D_DIM];
__device__ __half g_yh[M_PTS * D_DIM];
__device__ float g_b[M_PTS];
__device__ float g_partials[NBLOCKS];

__device__ __forceinline__ uint32_t smem_u32(const void* p) {
    uint32_t a;
    asm("{ .reg .u64 t; cvta.to.shared.u64 t, %1; cvt.u32.u64 %0, t; }" : "=r"(a) : "l"(p));
    return a;
}

#define CP_ASYNC16(s, g) \
    asm volatile("cp.async.cg.shared.global [%0], [%1], 16;" :: "r"(s), "l"(g))
#define CP_COMMIT() asm volatile("cp.async.commit_group;" ::: "memory")
#define CP_WAIT0()  asm volatile("cp.async.wait_group 0;" ::: "memory")

#define LDSM4(r, addr) \
    asm volatile("ldmatrix.sync.aligned.m8n8.x4.shared.b16 {%0,%1,%2,%3}, [%4];" \
                 : "=r"((r)[0]), "=r"((r)[1]), "=r"((r)[2]), "=r"((r)[3]) : "r"(addr))

#define MMA_F16(c, a, b0, b1) \
    asm volatile("mma.sync.aligned.m16n8k16.row.col.f32.f16.f16.f32 " \
                 "{%0,%1,%2,%3},{%4,%5,%6,%7},{%8,%9},{%0,%1,%2,%3};" \
                 : "+f"((c)[0]), "+f"((c)[1]), "+f"((c)[2]), "+f"((c)[3]) \
                 : "r"((a)[0]), "r"((a)[1]), "r"((a)[2]), "r"((a)[3]), "r"(b0), "r"(b1))

// ---------------------------------------------------------------------------
// Prep A: fp16 hi/lo split of x (vectorized, 4 elems/thread)
// ---------------------------------------------------------------------------
__global__ void prep_x_kernel(const float* __restrict__ x) {
    int i4 = blockIdx.x * blockDim.x + threadIdx.x;   // 0 .. N*D/4-1
    float4 v = ((const float4*)x)[i4];
    __half h0 = __float2half(v.x), h1 = __float2half(v.y);
    __half h2 = __float2half(v.z), h3 = __float2half(v.w);
    __half2* xh2 = (__half2*)g_xh;
    __half2* xl2 = (__half2*)g_xl;
    xh2[i4 * 2]     = __halves2half2(h0, h1);
    xh2[i4 * 2 + 1] = __halves2half2(h2, h3);
    xl2[i4 * 2]     = __halves2half2(__float2half(v.x - __half2float(h0)),
                                     __float2half(v.y - __half2float(h1)));
    xl2[i4 * 2 + 1] = __halves2half2(__float2half(v.z - __half2float(h2)),
                                     __float2half(v.w - __half2float(h3)));
}

// ---------------------------------------------------------------------------
// Prep B: fp16 y-hi; b_j = ||y_j||^2 - psi_j (fp32, exact)
// ---------------------------------------------------------------------------
__global__ void prep_y_kernel(const float* __restrict__ y,
                              const float* __restrict__ psi) {
    int i4 = blockIdx.x * blockDim.x + threadIdx.x;   // 0 .. M*D/4-1
    float4 v = ((const float4*)y)[i4];
    __half2* yh2 = (__half2*)g_yh;
    yh2[i4 * 2]     = __halves2half2(__float2half(v.x), __float2half(v.y));
    yh2[i4 * 2 + 1] = __halves2half2(__float2half(v.z), __float2half(v.w));
    int j = blockIdx.x * blockDim.x + threadIdx.x;
    if (j < M_PTS) {
        const float4* yr = (const float4*)(y + (size_t)j * D_DIM);
        float s = 0.f;
#pragma unroll
        for (int q = 0; q < 16; q++) {
            float4 w = yr[q];
            s = fmaf(w.x, w.x, s); s = fmaf(w.y, w.y, s);
            s = fmaf(w.z, w.z, s); s = fmaf(w.w, w.w, s);
        }
        g_b[j] = s - psi[j];
    }
}

// ---------------------------------------------------------------------------
// Main: fp16 2-pass mma (xh*yh + xl*yh), fused min-epilogue.
// 8 warps: wm = w>>2 (2), wn = w&3 (4); warp tile 64 x 32.
// SMEM tiles: 128 rows x 64 fp16 (128 B/row), 16B-chunk swizzle c ^ (row&7).
// ---------------------------------------------------------------------------
__global__ __launch_bounds__(256)
void semidual_mma_kernel(const float* __restrict__ x) {
    extern __shared__ char smem[];
    const uint32_t sb = smem_u32(smem);
    const int tid  = threadIdx.x;
    const int lane = tid & 31;
    const int w    = tid >> 5;
    const int wm   = w >> 2;
    const int wn   = w & 3;
    const int i0   = blockIdx.x * BM;

    // cp.async one [128 x 64] fp16 tile with swizzled stores (4 chunks/thread)
    auto tile_cp = [&](const __half* g, int row0, uint32_t soff) {
        const char* gp = (const char*)(g + (size_t)row0 * D_DIM);
#pragma unroll
        for (int it = 0; it < 4; it++) {
            int c   = it * 256 + tid;        // 0..1023
            int row = c >> 3, col = c & 7;
            uint32_t so = sb + soff + row * 128 + ((col ^ (row & 7)) << 4);
            CP_ASYNC16(so, gp + (size_t)c * 16);
        }
    };

    // prologue: x hi/lo tiles + y tile 0
    tile_cp(g_xh, i0, OFF_XH);
    tile_cp(g_xl, i0, OFF_XL);
    tile_cp(g_yh, 0, OFF_Y);
    CP_COMMIT();

    if (tid < BM) {
        const float4* xr = (const float4*)(x + (size_t)(i0 + tid) * D_DIM);
        float x2 = 0.f;
#pragma unroll
        for (int q = 0; q < 16; q++) {
            float4 v = xr[q];
            x2 = fmaf(v.x, v.x, x2); x2 = fmaf(v.y, v.y, x2);
            x2 = fmaf(v.z, v.z, x2); x2 = fmaf(v.w, v.w, x2);
        }
        ((float*)(smem + OFF_X2S))[tid] = x2;
        ((float*)(smem + OFF_BS))[tid] = g_b[tid];
    }
    CP_WAIT0();
    __syncthreads();

    // per-lane invariant addressing pieces
    const uint32_t aoff  = (uint32_t)(wm * 64 + (lane & 15)) * 128;
    const int      cselA = lane >> 4;
    const int      axorA = (lane & 7);
    const uint32_t boff  = (uint32_t)(wn * 32 + ((lane >> 4) << 3) + (lane & 7)) * 128;
    const int      cselB = (lane >> 3) & 1;
    const int      bxorB = (lane & 7);

    float rmin[8];
#pragma unroll
    for (int r = 0; r < 8; r++) rmin[r] = 3.4e38f;

    for (int t = 0; t < NTILES; t++) {
        const int b = t & 1, nb = b ^ 1;
        if (t + 1 < NTILES) {
            tile_cp(g_yh, (t + 1) * BN, OFF_Y + nb * 16384);
            CP_COMMIT();
            if (tid < BN)
                ((float*)(smem + OFF_BS))[nb * BN + tid] = g_b[(t + 1) * BN + tid];
        }

        const uint32_t yb  = sb + OFF_Y + b * 16384;
        const uint32_t axh = sb + OFF_XH;
        const uint32_t axl = sb + OFF_XL;

        float c[4][4][4];
#pragma unroll
        for (int mt = 0; mt < 4; mt++)
#pragma unroll
            for (int nt = 0; nt < 4; nt++)
#pragma unroll
                for (int q = 0; q < 4; q++) c[mt][nt][q] = 0.f;

#pragma unroll
        for (int kb = 0; kb < 4; kb++) {
            const uint32_t ca = (uint32_t)(((2 * kb + cselA) ^ axorA) << 4);
            const uint32_t cb = (uint32_t)(((2 * kb + cselB) ^ bxorB) << 4);
            uint32_t a[4][4], bb[2][4];
#pragma unroll
            for (int mt = 0; mt < 4; mt++) LDSM4(a[mt], axh + aoff + mt * 2048 + ca);
#pragma unroll
            for (int np = 0; np < 2; np++) LDSM4(bb[np], yb + boff + np * 2048 + cb);
            // pass 1: xh * yh
#pragma unroll
            for (int mt = 0; mt < 4; mt++)
#pragma unroll
                for (int nt = 0; nt < 4; nt++)
                    MMA_F16(c[mt][nt], a[mt], bb[nt >> 1][(nt & 1) * 2], bb[nt >> 1][(nt & 1) * 2 + 1]);
            // pass 2: xl * yh
#pragma unroll
            for (int mt = 0; mt < 4; mt++) LDSM4(a[mt], axl + aoff + mt * 2048 + ca);
#pragma unroll
            for (int mt = 0; mt < 4; mt++)
#pragma unroll
                for (int nt = 0; nt < 4; nt++)
                    MMA_F16(c[mt][nt], a[mt], bb[nt >> 1][(nt & 1) * 2], bb[nt >> 1][(nt & 1) * 2 + 1]);
        }

        // epilogue: min of (b_j - 2*dot) over this tile's cols (per lane: 8 rows)
        const float* bsf = (const float*)(smem + OFF_BS) + b * BN;
#pragma unroll
        for (int nt = 0; nt < 4; nt++) {
            const int j0 = wn * 32 + nt * 8 + (lane & 3) * 2;
            const float b0 = bsf[j0], b1 = bsf[j0 + 1];
#pragma unroll
            for (int mt = 0; mt < 4; mt++) {
                float v0 = fminf(fmaf(-2.f, c[mt][nt][0], b0), fmaf(-2.f, c[mt][nt][1], b1));
                float v1 = fminf(fmaf(-2.f, c[mt][nt][2], b0), fmaf(-2.f, c[mt][nt][3], b1));
                rmin[mt * 2]     = fminf(rmin[mt * 2], v0);
                rmin[mt * 2 + 1] = fminf(rmin[mt * 2 + 1], v1);
            }
        }

        CP_WAIT0();
        __syncthreads();
    }

    // min across the 4 j-lanes of each row group
#pragma unroll
    for (int r = 0; r < 8; r++) {
        rmin[r] = fminf(rmin[r], __shfl_xor_sync(0xffffffffu, rmin[r], 1));
        rmin[r] = fminf(rmin[r], __shfl_xor_sync(0xffffffffu, rmin[r], 2));
    }
    float* rowred = (float*)(smem + OFF_ROWRED);
    if ((lane & 3) == 0) {
        const int g = lane >> 2;
#pragma unroll
        for (int mt = 0; mt < 4; mt++) {
            const int r0 = wm * 64 + mt * 16 + g;
            rowred[wn * BM + r0]     = rmin[mt * 2];
            rowred[wn * BM + r0 + 8] = rmin[mt * 2 + 1];
        }
    }
    __syncthreads();
    if (tid < BM) {
        float m = fminf(fminf(rowred[tid], rowred[BM + tid]),
                        fminf(rowred[2 * BM + tid], rowred[3 * BM + tid]));
        float v = ((const float*)(smem + OFF_X2S))[tid] + m;
#pragma unroll
        for (int s = 16; s >= 1; s >>= 1) v += __shfl_xor_sync(0xffffffffu, v, s);
        if (lane == 0) ((float*)(smem + OFF_RED))[tid >> 5] = v;
    }
    __syncthreads();
    if (tid == 0) {
        const float* rd = (const float*)(smem + OFF_RED);
        g_partials[blockIdx.x] = rd[0] + rd[1] + rd[2] + rd[3];
    }
}

// ---------------------------------------------------------------------------
// Finalize: deterministic reduction + mean(psi)
// ---------------------------------------------------------------------------
__global__ void finalize_kernel(const float* __restrict__ psi,
                                float* __restrict__ out) {
    __shared__ float sh[256];
    int tid = threadIdx.x;
    float s = 0.f;
    for (int b = tid; b < NBLOCKS; b += 256) s += g_partials[b];
    s *= (1.0f / N_PTS);
    float p = 0.f;
    for (int j = tid; j < M_PTS; j += 256) p += psi[j];
    s = fmaf(p, 1.0f / M_PTS, s);
    sh[tid] = s;
    __syncthreads();
    for (int off = 128; off > 0; off >>= 1) {
        if (tid < off) sh[tid] += sh[tid + off];
        __syncthreads();
    }
    if (tid == 0) out[0] = sh[0];
}

extern "C" void kernel_launch(void* const* d_in, const int* in_sizes, int n_in,
                              void* d_out, int out_size) {
    (void)in_sizes; (void)n_in; (void)out_size;
    const float* x   = (const float*)d_in[0];   // [N, D]
    const float* y   = (const float*)d_in[1];   // [M, D]
    const float* psi = (const float*)d_in[2];   // [M]
    float* out = (float*)d_out;

    cudaFuncSetAttribute(semidual_mma_kernel,
                         cudaFuncAttributeMaxDynamicSharedMemorySize, SMEM_TOTAL);

    prep_x_kernel<<<(N_PTS * D_DIM / 4) / 256, 256>>>(x);
    prep_y_kernel<<<(M_PTS * D_DIM / 4) / 256, 256>>>(y, psi);
    semidual_mma_kernel<<<NBLOCKS, 256, SMEM_TOTAL>>>(x);
    finalize_kernel<<<1, 256>>>(psi, out);
}

// round 6
// speedup vs baseline: 5.1010x; 1.0827x over previous
#include <cuda_runtime.h>
#include <cuda_fp16.h>
#include <cstdint>

#define N_PTS 32768
#define M_PTS 8192
#define D_DIM 64
#define BM 128
#define BN 128
#define NTILES (M_PTS / BN)          // 64
#define NBLOCKS (N_PTS / BM)         // 256

// dynamic smem layout (bytes)
#define OFF_XH     0                 // 16384
#define OFF_Y      16384             // 2 * 16384 (double-buffered y-hi)
#define OFF_BS     49152             // 2 * 128 * 4
#define OFF_X2S    50176             // 128 * 4
#define OFF_ROWRED 50688             // 4 * 128 * 4
#define OFF_RED    52736             // 16
#define SMEM_TOTAL 52800

__device__ __half g_xh[N_PTS * D_DIM];
__device__ __half g_yh[M_PTS * D_DIM];
__device__ float g_b[M_PTS];
__device__ float g_partials[NBLOCKS];

__device__ __forceinline__ uint32_t smem_u32(const void* p) {
    uint32_t a;
    asm("{ .reg .u64 t; cvta.to.shared.u64 t, %1; cvt.u32.u64 %0, t; }" : "=r"(a) : "l"(p));
    return a;
}

#define CP_ASYNC16(s, g) \
    asm volatile("cp.async.cg.shared.global [%0], [%1], 16;" :: "r"(s), "l"(g))
#define CP_COMMIT() asm volatile("cp.async.commit_group;" ::: "memory")
#define CP_WAIT0()  asm volatile("cp.async.wait_group 0;" ::: "memory")

#define LDSM4(r, addr) \
    asm volatile("ldmatrix.sync.aligned.m8n8.x4.shared.b16 {%0,%1,%2,%3}, [%4];" \
                 : "=r"((r)[0]), "=r"((r)[1]), "=r"((r)[2]), "=r"((r)[3]) : "r"(addr))

#define MMA_F16(c, a, b0, b1) \
    asm volatile("mma.sync.aligned.m16n8k16.row.col.f32.f16.f16.f32 " \
                 "{%0,%1,%2,%3},{%4,%5,%6,%7},{%8,%9},{%0,%1,%2,%3};" \
                 : "+f"((c)[0]), "+f"((c)[1]), "+f"((c)[2]), "+f"((c)[3]) \
                 : "r"((a)[0]), "r"((a)[1]), "r"((a)[2]), "r"((a)[3]), "r"(b0), "r"(b1))

// ---------------------------------------------------------------------------
// Prep: fp16 conversion of x and y; b_j = ||y_j||^2 - psi_j (fp32, exact)
// ---------------------------------------------------------------------------
__global__ void prep_kernel(const float* __restrict__ x,
                            const float* __restrict__ y,
                            const float* __restrict__ psi) {
    int i4 = blockIdx.x * blockDim.x + threadIdx.x;   // 0 .. N*D/4-1
    {
        float4 v = ((const float4*)x)[i4];
        __half2* xh2 = (__half2*)g_xh;
        xh2[i4 * 2]     = __halves2half2(__float2half(v.x), __float2half(v.y));
        xh2[i4 * 2 + 1] = __halves2half2(__float2half(v.z), __float2half(v.w));
    }
    if (i4 < M_PTS * D_DIM / 4) {
        float4 v = ((const float4*)y)[i4];
        __half2* yh2 = (__half2*)g_yh;
        yh2[i4 * 2]     = __halves2half2(__float2half(v.x), __float2half(v.y));
        yh2[i4 * 2 + 1] = __halves2half2(__float2half(v.z), __float2half(v.w));
    }
    if (i4 < M_PTS) {
        const float4* yr = (const float4*)(y + (size_t)i4 * D_DIM);
        float s = 0.f;
#pragma unroll
        for (int q = 0; q < 16; q++) {
            float4 w = yr[q];
            s = fmaf(w.x, w.x, s); s = fmaf(w.y, w.y, s);
            s = fmaf(w.z, w.z, s); s = fmaf(w.w, w.w, s);
        }
        g_b[i4] = s - psi[i4];
    }
}

// ---------------------------------------------------------------------------
// Main: single-pass fp16 mma (xh*yh), fused min-epilogue.
// 8 warps: wm = w>>2 (2), wn = w&3 (4); warp tile 64 x 32.
// SMEM tiles: 128 rows x 64 fp16 (128 B/row), 16B-chunk swizzle c ^ (row&7).
// ---------------------------------------------------------------------------
__global__ __launch_bounds__(256, 2)
void semidual_mma_kernel(const float* __restrict__ x) {
    extern __shared__ char smem[];
    const uint32_t sb = smem_u32(smem);
    const int tid  = threadIdx.x;
    const int lane = tid & 31;
    const int w    = tid >> 5;
    const int wm   = w >> 2;
    const int wn   = w & 3;
    const int i0   = blockIdx.x * BM;

    // cp.async one [128 x 64] fp16 tile with swizzled stores (4 chunks/thread)
    auto tile_cp = [&](const __half* g, int row0, uint32_t soff) {
        const char* gp = (const char*)(g + (size_t)row0 * D_DIM);
#pragma unroll
        for (int it = 0; it < 4; it++) {
            int c   = it * 256 + tid;        // 0..1023
            int row = c >> 3, col = c & 7;
            uint32_t so = sb + soff + row * 128 + ((col ^ (row & 7)) << 4);
            CP_ASYNC16(so, gp + (size_t)c * 16);
        }
    };

    // prologue: x tile + y tile 0
    tile_cp(g_xh, i0, OFF_XH);
    tile_cp(g_yh, 0, OFF_Y);
    CP_COMMIT();

    if (tid < BM) {
        const float4* xr = (const float4*)(x + (size_t)(i0 + tid) * D_DIM);
        float x2 = 0.f;
#pragma unroll
        for (int q = 0; q < 16; q++) {
            float4 v = xr[q];
            x2 = fmaf(v.x, v.x, x2); x2 = fmaf(v.y, v.y, x2);
            x2 = fmaf(v.z, v.z, x2); x2 = fmaf(v.w, v.w, x2);
        }
        ((float*)(smem + OFF_X2S))[tid] = x2;
        ((float*)(smem + OFF_BS))[tid] = g_b[tid];
    }
    CP_WAIT0();
    __syncthreads();

    // per-lane invariant addressing pieces
    const uint32_t aoff  = (uint32_t)(wm * 64 + (lane & 15)) * 128;
    const int      cselA = lane >> 4;
    const int      axorA = (lane & 7);
    const uint32_t boff  = (uint32_t)(wn * 32 + ((lane >> 4) << 3) + (lane & 7)) * 128;
    const int      cselB = (lane >> 3) & 1;
    const int      bxorB = (lane & 7);

    float rmin[8];
#pragma unroll
    for (int r = 0; r < 8; r++) rmin[r] = 3.4e38f;

    for (int t = 0; t < NTILES; t++) {
        const int b = t & 1, nb = b ^ 1;
        if (t + 1 < NTILES) {
            tile_cp(g_yh, (t + 1) * BN, OFF_Y + nb * 16384);
            CP_COMMIT();
            if (tid < BN)
                ((float*)(smem + OFF_BS))[nb * BN + tid] = g_b[(t + 1) * BN + tid];
        }

        const uint32_t yb  = sb + OFF_Y + b * 16384;
        const uint32_t axh = sb + OFF_XH;

        float c[4][4][4];
#pragma unroll
        for (int mt = 0; mt < 4; mt++)
#pragma unroll
            for (int nt = 0; nt < 4; nt++)
#pragma unroll
                for (int q = 0; q < 4; q++) c[mt][nt][q] = 0.f;

#pragma unroll
        for (int kb = 0; kb < 4; kb++) {
            const uint32_t ca = (uint32_t)(((2 * kb + cselA) ^ axorA) << 4);
            const uint32_t cb = (uint32_t)(((2 * kb + cselB) ^ bxorB) << 4);
            uint32_t a[4][4], bb[2][4];
#pragma unroll
            for (int mt = 0; mt < 4; mt++) LDSM4(a[mt], axh + aoff + mt * 2048 + ca);
#pragma unroll
            for (int np = 0; np < 2; np++) LDSM4(bb[np], yb + boff + np * 2048 + cb);
#pragma unroll
            for (int mt = 0; mt < 4; mt++)
#pragma unroll
                for (int nt = 0; nt < 4; nt++)
                    MMA_F16(c[mt][nt], a[mt], bb[nt >> 1][(nt & 1) * 2], bb[nt >> 1][(nt & 1) * 2 + 1]);
        }

        // epilogue: min of (b_j - 2*dot) over this tile's cols (per lane: 8 rows)
        const float* bsf = (const float*)(smem + OFF_BS) + b * BN;
#pragma unroll
        for (int nt = 0; nt < 4; nt++) {
            const int j0 = wn * 32 + nt * 8 + (lane & 3) * 2;
            const float b0 = bsf[j0], b1 = bsf[j0 + 1];
#pragma unroll
            for (int mt = 0; mt < 4; mt++) {
                float v0 = fminf(fmaf(-2.f, c[mt][nt][0], b0), fmaf(-2.f, c[mt][nt][1], b1));
                float v1 = fminf(fmaf(-2.f, c[mt][nt][2], b0), fmaf(-2.f, c[mt][nt][3], b1));
                rmin[mt * 2]     = fminf(rmin[mt * 2], v0);
                rmin[mt * 2 + 1] = fminf(rmin[mt * 2 + 1], v1);
            }
        }

        CP_WAIT0();
        __syncthreads();
    }

    // min across the 4 j-lanes of each row group
#pragma unroll
    for (int r = 0; r < 8; r++) {
        rmin[r] = fminf(rmin[r], __shfl_xor_sync(0xffffffffu, rmin[r], 1));
        rmin[r] = fminf(rmin[r], __shfl_xor_sync(0xffffffffu, rmin[r], 2));
    }
    float* rowred = (float*)(smem + OFF_ROWRED);
    if ((lane & 3) == 0) {
        const int g = lane >> 2;
#pragma unroll
        for (int mt = 0; mt < 4; mt++) {
            const int r0 = wm * 64 + mt * 16 + g;
            rowred[wn * BM + r0]     = rmin[mt * 2];
            rowred[wn * BM + r0 + 8] = rmin[mt * 2 + 1];
        }
    }
    __syncthreads();
    if (tid < BM) {
        float m = fminf(fminf(rowred[tid], rowred[BM + tid]),
                        fminf(rowred[2 * BM + tid], rowred[3 * BM + tid]));
        float v = ((const float*)(smem + OFF_X2S))[tid] + m;
#pragma unroll
        for (int s = 16; s >= 1; s >>= 1) v += __shfl_xor_sync(0xffffffffu, v, s);
        if (lane == 0) ((float*)(smem + OFF_RED))[tid >> 5] = v;
    }
    __syncthreads();
    if (tid == 0) {
        const float* rd = (const float*)(smem + OFF_RED);
        g_partials[blockIdx.x] = rd[0] + rd[1] + rd[2] + rd[3];
    }
}

// ---------------------------------------------------------------------------
// Finalize: deterministic reduction + mean(psi), vectorized
// ---------------------------------------------------------------------------
__global__ void finalize_kernel(const float* __restrict__ psi,
                                float* __restrict__ out) {
    __shared__ float sh[256];
    int tid = threadIdx.x;
    float s = 0.f;
    for (int b = tid; b < NBLOCKS; b += 256) s += g_partials[b];
    s *= (1.0f / N_PTS);
    float p = 0.f;
    const float4* p4 = (const float4*)psi;
#pragma unroll
    for (int q = 0; q < M_PTS / 4 / 256; q++) {
        float4 v = p4[q * 256 + tid];
        p += (v.x + v.y) + (v.z + v.w);
    }
    s = fmaf(p, 1.0f / M_PTS, s);
    sh[tid] = s;
    __syncthreads();
    for (int off = 128; off > 0; off >>= 1) {
        if (tid < off) sh[tid] += sh[tid + off];
        __syncthreads();
    }
    if (tid == 0) out[0] = sh[0];
}

extern "C" void kernel_launch(void* const* d_in, const int* in_sizes, int n_in,
                              void* d_out, int out_size) {
    (void)in_sizes; (void)n_in; (void)out_size;
    const float* x   = (const float*)d_in[0];   // [N, D]
    const float* y   = (const float*)d_in[1];   // [M, D]
    const float* psi = (const float*)d_in[2];   // [M]
    float* out = (float*)d_out;

    cudaFuncSetAttribute(semidual_mma_kernel,
                         cudaFuncAttributeMaxDynamicSharedMemorySize, SMEM_TOTAL);

    prep_kernel<<<(N_PTS * D_DIM / 4) / 256, 256>>>(x, y, psi);
    semidual_mma_kernel<<<NBLOCKS, 256, SMEM_TOTAL>>>(x);
    finalize_kernel<<<1, 256>>>(psi, out);
}

// round 10
// speedup vs baseline: 7.6916x; 1.5078x over previous
#include <cuda_runtime.h>
#include <cuda_fp16.h>
#include <cstdint>

#define N_PTS 32768
#define M_PTS 8192
#define D_DIM 64
#define BM 128
#define BN 128
#define NTILES (M_PTS / BN)          // 64
#define NBLOCKS (N_PTS / BM)         // 256

// dynamic smem layout (bytes)
#define OFF_XH     0                 // 16384
#define OFF_Y      16384             // 3 * 16384 (triple-buffered y)
#define OFF_BS     65536             // 3 * 128 * 4
#define OFF_X2S    67072             // 128 * 4
#define OFF_ROWRED 67584             // 4 * 128 * 4
#define OFF_RED    69632             // 16
#define SMEM_TOTAL 69648

__device__ __half g_yh[M_PTS * D_DIM];
__device__ float g_b[M_PTS];
__device__ float g_partials[NBLOCKS];

__device__ __forceinline__ uint32_t smem_u32(const void* p) {
    uint32_t a;
    asm("{ .reg .u64 t; cvta.to.shared.u64 t, %1; cvt.u32.u64 %0, t; }" : "=r"(a) : "l"(p));
    return a;
}

__device__ __forceinline__ uint32_t h2_u32(__half2 h) {
    uint32_t u;
    *reinterpret_cast<__half2*>(&u) = h;
    return u;
}

#define CP_ASYNC16(s, g) \
    asm volatile("cp.async.cg.shared.global [%0], [%1], 16;" :: "r"(s), "l"(g))
#define CP_COMMIT()  asm volatile("cp.async.commit_group;" ::: "memory")
#define CP_WAIT(N)   asm volatile("cp.async.wait_group %0;" :: "n"(N) : "memory")

#define LDSM4(r, addr) \
    asm volatile("ldmatrix.sync.aligned.m8n8.x4.shared.b16 {%0,%1,%2,%3}, [%4];" \
                 : "=r"((r)[0]), "=r"((r)[1]), "=r"((r)[2]), "=r"((r)[3]) : "r"(addr))

#define MMA_F16(c, a, b0, b1) \
    asm volatile("mma.sync.aligned.m16n8k16.row.col.f32.f16.f16.f32 " \
                 "{%0,%1,%2,%3},{%4,%5,%6,%7},{%8,%9},{%0,%1,%2,%3};" \
                 : "+f"((c)[0]), "+f"((c)[1]), "+f"((c)[2]), "+f"((c)[3]) \
                 : "r"((a)[0]), "r"((a)[1]), "r"((a)[2]), "r"((a)[3]), "r"(b0), "r"(b1))

// ---------------------------------------------------------------------------
// Prep: fp16 conversion of y; b_j = ||y_j||^2 - psi_j (fp32, exact)
// ---------------------------------------------------------------------------
__global__ void prep_y_kernel(const float* __restrict__ y,
                              const float* __restrict__ psi) {
    int i4 = blockIdx.x * blockDim.x + threadIdx.x;   // 0 .. M*D/4-1
    float4 v = ((const float4*)y)[i4];
    __half2* yh2 = (__half2*)g_yh;
    yh2[i4 * 2]     = __halves2half2(__float2half(v.x), __float2half(v.y));
    yh2[i4 * 2 + 1] = __halves2half2(__float2half(v.z), __float2half(v.w));
    if (i4 < M_PTS) {
        const float4* yr = (const float4*)(y + (size_t)i4 * D_DIM);
        float s = 0.f;
#pragma unroll
        for (int q = 0; q < 16; q++) {
            float4 w = yr[q];
            s = fmaf(w.x, w.x, s); s = fmaf(w.y, w.y, s);
            s = fmaf(w.z, w.z, s); s = fmaf(w.w, w.w, s);
        }
        g_b[i4] = s - psi[i4];
    }
}

// ---------------------------------------------------------------------------
// Main: single-pass fp16 mma, register-lean chunked accumulation,
// triple-buffered y with cp.async.wait_group 1, one barrier per tile.
// 8 warps: wm = w>>2 (2), wn = w&3 (4); warp tile 64 x 32 in two 32x32 chunks.
// ---------------------------------------------------------------------------
__global__ __launch_bounds__(256, 2)
void semidual_mma_kernel(const float* __restrict__ x) {
    extern __shared__ char smem[];
    const uint32_t sb = smem_u32(smem);
    const int tid  = threadIdx.x;
    const int lane = tid & 31;
    const int w    = tid >> 5;
    const int wm   = w >> 2;
    const int wn   = w & 3;
    const int i0   = blockIdx.x * BM;

    // cp.async one [128 x 64] fp16 y-tile with swizzled stores
    auto tile_cp = [&](int row0, uint32_t soff) {
        const char* gp = (const char*)(g_yh + (size_t)row0 * D_DIM);
#pragma unroll
        for (int it = 0; it < 4; it++) {
            int c   = it * 256 + tid;        // 0..1023
            int row = c >> 3, col = c & 7;
            uint32_t so = sb + soff + row * 128 + ((col ^ (row & 7)) << 4);
            CP_ASYNC16(so, gp + (size_t)c * 16);
        }
    };

    // convert x tile fp32 -> fp16 directly into swizzled smem
    {
        const float4* x4 = (const float4*)(x + (size_t)i0 * D_DIM);
#pragma unroll
        for (int it = 0; it < 4; it++) {
            int c   = it * 256 + tid;        // chunk 0..1023
            int row = c >> 3, col8 = c & 7;
            float4 v0 = x4[row * 16 + col8 * 2];
            float4 v1 = x4[row * 16 + col8 * 2 + 1];
            uint4 h;
            h.x = h2_u32(__halves2half2(__float2half(v0.x), __float2half(v0.y)));
            h.y = h2_u32(__halves2half2(__float2half(v0.z), __float2half(v0.w)));
            h.z = h2_u32(__halves2half2(__float2half(v1.x), __float2half(v1.y)));
            h.w = h2_u32(__halves2half2(__float2half(v1.z), __float2half(v1.w)));
            *(uint4*)(smem + OFF_XH + row * 128 + ((col8 ^ (row & 7)) << 4)) = h;
        }
    }

    // prologue: y tiles 0 and 1 as separate groups; bs slots 0,1; x2
    tile_cp(0, OFF_Y);
    CP_COMMIT();
    tile_cp(BN, OFF_Y + 16384);
    CP_COMMIT();
    if (tid < BM) {
        ((float*)(smem + OFF_BS))[tid]      = g_b[tid];
        ((float*)(smem + OFF_BS))[BN + tid] = g_b[BN + tid];
        const float4* xr = (const float4*)(x + (size_t)(i0 + tid) * D_DIM);
        float x2 = 0.f;
#pragma unroll
        for (int q = 0; q < 16; q++) {
            float4 v = xr[q];
            x2 = fmaf(v.x, v.x, x2); x2 = fmaf(v.y, v.y, x2);
            x2 = fmaf(v.z, v.z, x2); x2 = fmaf(v.w, v.w, x2);
        }
        ((float*)(smem + OFF_X2S))[tid] = x2;
    }

    // per-lane invariant addressing pieces
    const uint32_t aoff  = (uint32_t)(wm * 64 + (lane & 15)) * 128;
    const int      cselA = lane >> 4;
    const int      axorA = (lane & 7);
    const uint32_t boff  = (uint32_t)(wn * 32 + ((lane >> 4) << 3) + (lane & 7)) * 128;
    const int      cselB = (lane >> 3) & 1;
    const int      bxorB = (lane & 7);
    const int      j0b   = wn * 32 + (lane & 3) * 2;

    float rmin[8];
#pragma unroll
    for (int r = 0; r < 8; r++) rmin[r] = 3.4e38f;

    for (int t = 0; t < NTILES; t++) {
        const int b = t % 3;
        if (t + 1 < NTILES) {
            const int nb = (t + 1) % 3;
            tile_cp((t + 1) * BN, OFF_Y + nb * 16384);
            CP_COMMIT();
            if (tid < BN)
                ((float*)(smem + OFF_BS))[nb * BN + tid] = g_b[(t + 1) * BN + tid];
            CP_WAIT(1);
        } else {
            CP_WAIT(0);
        }
        __syncthreads();

        const uint32_t yb  = sb + OFF_Y + b * 16384;
        const uint32_t axh = sb + OFF_XH;
        const float* bsf = (const float*)(smem + OFF_BS) + b * BN;

#pragma unroll
        for (int mtc = 0; mtc < 2; mtc++) {
            float c[2][4][4];
#pragma unroll
            for (int mt = 0; mt < 2; mt++)
#pragma unroll
                for (int nt = 0; nt < 4; nt++)
#pragma unroll
                    for (int q = 0; q < 4; q++) c[mt][nt][q] = 0.f;

#pragma unroll
            for (int kb = 0; kb < 4; kb++) {
                const uint32_t ca = (uint32_t)(((2 * kb + cselA) ^ axorA) << 4);
                const uint32_t cb = (uint32_t)(((2 * kb + cselB) ^ bxorB) << 4);
                uint32_t a[2][4], bb[2][4];
#pragma unroll
                for (int mt = 0; mt < 2; mt++)
                    LDSM4(a[mt], axh + aoff + (mtc * 2 + mt) * 2048 + ca);
#pragma unroll
                for (int np = 0; np < 2; np++)
                    LDSM4(bb[np], yb + boff + np * 2048 + cb);
#pragma unroll
                for (int mt = 0; mt < 2; mt++)
#pragma unroll
                    for (int nt = 0; nt < 4; nt++)
                        MMA_F16(c[mt][nt], a[mt], bb[nt >> 1][(nt & 1) * 2], bb[nt >> 1][(nt & 1) * 2 + 1]);
            }

            // fold this m-chunk into rmin
#pragma unroll
            for (int nt = 0; nt < 4; nt++) {
                const float b0 = bsf[j0b + nt * 8];
                const float b1 = bsf[j0b + nt * 8 + 1];
#pragma unroll
                for (int mt = 0; mt < 2; mt++) {
                    const int mi = mtc * 2 + mt;
                    float v0 = fminf(fmaf(-2.f, c[mt][nt][0], b0), fmaf(-2.f, c[mt][nt][1], b1));
                    float v1 = fminf(fmaf(-2.f, c[mt][nt][2], b0), fmaf(-2.f, c[mt][nt][3], b1));
                    rmin[mi * 2]     = fminf(rmin[mi * 2], v0);
                    rmin[mi * 2 + 1] = fminf(rmin[mi * 2 + 1], v1);
                }
            }
        }
    }

    // min across the 4 j-lanes of each row group
#pragma unroll
    for (int r = 0; r < 8; r++) {
        rmin[r] = fminf(rmin[r], __shfl_xor_sync(0xffffffffu, rmin[r], 1));
        rmin[r] = fminf(rmin[r], __shfl_xor_sync(0xffffffffu, rmin[r], 2));
    }
    float* rowred = (float*)(smem + OFF_ROWRED);
    __syncthreads();
    if ((lane & 3) == 0) {
        const int g = lane >> 2;
#pragma unroll
        for (int mt = 0; mt < 4; mt++) {
            const int r0 = wm * 64 + mt * 16 + g;
            rowred[wn * BM + r0]     = rmin[mt * 2];
            rowred[wn * BM + r0 + 8] = rmin[mt * 2 + 1];
        }
    }
    __syncthreads();
    if (tid < BM) {
        float m = fminf(fminf(rowred[tid], rowred[BM + tid]),
                        fminf(rowred[2 * BM + tid], rowred[3 * BM + tid]));
        float v = ((const float*)(smem + OFF_X2S))[tid] + m;
#pragma unroll
        for (int s = 16; s >= 1; s >>= 1) v += __shfl_xor_sync(0xffffffffu, v, s);
        if (lane == 0) ((float*)(smem + OFF_RED))[tid >> 5] = v;
    }
    __syncthreads();
    if (tid == 0) {
        const float* rd = (const float*)(smem + OFF_RED);
        g_partials[blockIdx.x] = rd[0] + rd[1] + rd[2] + rd[3];
    }
}

// ---------------------------------------------------------------------------
// Finalize: deterministic reduction + mean(psi), vectorized
// ---------------------------------------------------------------------------
__global__ void finalize_kernel(const float* __restrict__ psi,
                                float* __restrict__ out) {
    __shared__ float sh[256];
    int tid = threadIdx.x;
    float s = 0.f;
    for (int b = tid; b < NBLOCKS; b += 256) s += g_partials[b];
    s *= (1.0f / N_PTS);
    float p = 0.f;
    const float4* p4 = (const float4*)psi;
#pragma unroll
    for (int q = 0; q < M_PTS / 4 / 256; q++) {
        float4 v = p4[q * 256 + tid];
        p += (v.x + v.y) + (v.z + v.w);
    }
    s = fmaf(p, 1.0f / M_PTS, s);
    sh[tid] = s;
    __syncthreads();
    for (int off = 128; off > 0; off >>= 1) {
        if (tid < off) sh[tid] += sh[tid + off];
        __syncthreads();
    }
    if (tid == 0) out[0] = sh[0];
}

extern "C" void kernel_launch(void* const* d_in, const int* in_sizes, int n_in,
                              void* d_out, int out_size) {
    (void)in_sizes; (void)n_in; (void)out_size;
    const float* x   = (const float*)d_in[0];   // [N, D]
    const float* y   = (const float*)d_in[1];   // [M, D]
    const float* psi = (const float*)d_in[2];   // [M]
    float* out = (float*)d_out;

    cudaFuncSetAttribute(semidual_mma_kernel,
                         cudaFuncAttributeMaxDynamicSharedMemorySize, SMEM_TOTAL);

    prep_y_kernel<<<(M_PTS * D_DIM / 4) / 256, 256>>>(y, psi);
    semidual_mma_kernel<<<NBLOCKS, 256, SMEM_TOTAL>>>(x);
    finalize_kernel<<<1, 256>>>(psi, out);
}